// round 9
// baseline (speedup 1.0000x reference)
#include <cuda_runtime.h>

#define NB 8
#define NV 100000
#define NF 200000
#define BN (NB * NV)
#define TOTF (NB * NF)

// scratch: per-vertex accumulator (x, y, z, deg) — 12.8 MB, L2-resident
__device__ float4 g_acc[BN];
// padded, 16B-aligned copy of V for single-LDG.128 gathers
__device__ float4 g_V4[BN];
__device__ int g_is32;   // 1 if F is int32, 0 if int64

// Fused prep: dtype detect (parallel, warp 0 of block 0) + zero accumulators
// + pad V into float4 staging. 4 vertices per thread, float4-coalesced.
__global__ void __launch_bounds__(256) prep_k(const float* __restrict__ V,
                                              const long long* __restrict__ F64,
                                              int nwords) {
    int t = blockIdx.x * blockDim.x + threadIdx.x;

    // Parallel dtype detection: 32 lanes x 32 strided words, all loads batched.
    if (blockIdx.x == 0 && threadIdx.x < 32) {
        int lane = threadIdx.x;
        int bad = 0;
        int n = nwords < 1024 ? nwords : 1024;
        #pragma unroll
        for (int k = 0; k < 32; k++) {
            int i = lane + k * 32;
            if (i < n) {
                long long v = F64[i];
                bad |= (v < 0 || v >= NV) ? 1 : 0;
            }
        }
        unsigned m = __ballot_sync(0xFFFFFFFFu, bad);
        if (lane == 0) g_is32 = (m != 0) ? 1 : 0;
    }

    int v0 = t * 4;
    if (v0 >= BN) return;
    // read 12 consecutive floats (48B, 16B-aligned) as three float4
    const float4* src = (const float4*)(V + (size_t)v0 * 3);
    float4 a = src[0];
    float4 b = src[1];
    float4 c = src[2];
    float4 z = make_float4(0.f, 0.f, 0.f, 0.f);
    g_V4[v0 + 0] = make_float4(a.x, a.y, a.z, 0.f);
    g_V4[v0 + 1] = make_float4(a.w, b.x, b.y, 0.f);
    g_V4[v0 + 2] = make_float4(b.z, b.w, c.x, 0.f);
    g_V4[v0 + 3] = make_float4(c.y, c.z, c.w, 0.f);
    g_acc[v0 + 0] = z;
    g_acc[v0 + 1] = z;
    g_acc[v0 + 2] = z;
    g_acc[v0 + 3] = z;
}

__device__ __forceinline__ int clampi(int v, int lo, int hi) {
    return v < lo ? lo : (v > hi ? hi : v);
}

__device__ __forceinline__ void red_v4(float4* addr, float x, float y, float z, float w) {
    asm volatile("red.global.add.v4.f32 [%0], {%1, %2, %3, %4};"
                 :: "l"(addr), "f"(x), "f"(y), "f"(z), "f"(w)
                 : "memory");
}

__global__ void __launch_bounds__(256) face_k(const void* __restrict__ Fraw) {
    int t = blockIdx.x * blockDim.x + threadIdx.x;
    if (t >= TOTF) return;
    int b = t / NF;
    int base = b * NV;

    int f0, f1, f2;
    if (g_is32) {
        const int* fp = (const int*)Fraw + (size_t)t * 3;
        f0 = fp[0]; f1 = fp[1]; f2 = fp[2];
    } else {
        const long long* fp = (const long long*)Fraw + (size_t)t * 3;
        f0 = (int)fp[0]; f1 = (int)fp[1]; f2 = (int)fp[2];
    }
    f0 = clampi(f0, 0, NV - 1);
    f1 = clampi(f1, 0, NV - 1);
    f2 = clampi(f2, 0, NV - 1);

    int i0 = base + f0, i1 = base + f1, i2 = base + f2;

    float4 P0 = __ldg(&g_V4[i0]);
    float4 P1 = __ldg(&g_V4[i1]);
    float4 P2 = __ldg(&g_V4[i2]);
    float x0 = P0.x, y0 = P0.y, z0 = P0.z;
    float x1 = P1.x, y1 = P1.y, z1 = P1.z;
    float x2 = P2.x, y2 = P2.y, z2 = P2.z;

    // squared edge lengths (reference: l1=|v1-v2|, l2=|v2-v0|, l3=|v0-v1|)
    float ax = x1 - x2, ay = y1 - y2, az = z1 - z2;
    float bx = x2 - x0, by = y2 - y0, bz = z2 - z0;
    float cx = x0 - x1, cy = y0 - y1, cz = z0 - z1;
    float d1 = ax * ax + ay * ay + az * az;
    float d2 = bx * bx + by * by + bz * bz;
    float d3 = cx * cx + cy * cy + cz * cz;
    float l1 = sqrtf(d1), l2 = sqrtf(d2), l3 = sqrtf(d3);
    float sp = 0.5f * (l1 + l2 + l3);
    float inside = sp * (sp - l1) * (sp - l2) * (sp - l3);
    inside = fmaxf(inside, 0.0f);
    float A = 2.0f * sqrtf(inside);
    float inv = 0.25f / (A + 1e-10f);
    if (A == 0.0f) inv = 0.0f;

    float w23 = (d2 + d3 - d1) * inv;  // edge (v1,v2)
    float w31 = (d1 + d3 - d2) * inv;  // edge (v2,v0)
    float w12 = (d1 + d2 - d3) * inv;  // edge (v0,v1)

    red_v4(&g_acc[i0], w31 * x2 + w12 * x1, w31 * y2 + w12 * y1,
                       w31 * z2 + w12 * z1, w31 + w12);
    red_v4(&g_acc[i1], w23 * x2 + w12 * x0, w23 * y2 + w12 * y0,
                       w23 * z2 + w12 * z0, w23 + w12);
    red_v4(&g_acc[i2], w23 * x1 + w31 * x0, w23 * y1 + w31 * y0,
                       w23 * z1 + w31 * z0, w23 + w31);
}

// out[v] = acc[v].xyz - acc[v].w * V[v], 4 vertices per thread,
// fully float4-coalesced loads and stores.
__global__ void __launch_bounds__(256) fin_k(float* __restrict__ out) {
    int t = blockIdx.x * blockDim.x + threadIdx.x;
    int v0 = t * 4;
    if (v0 >= BN) return;

    float4 a0 = g_acc[v0 + 0], p0 = g_V4[v0 + 0];
    float4 a1 = g_acc[v0 + 1], p1 = g_V4[v0 + 1];
    float4 a2 = g_acc[v0 + 2], p2 = g_V4[v0 + 2];
    float4 a3 = g_acc[v0 + 3], p3 = g_V4[v0 + 3];

    float r0 = a0.x - a0.w * p0.x;
    float r1 = a0.y - a0.w * p0.y;
    float r2 = a0.z - a0.w * p0.z;
    float r3 = a1.x - a1.w * p1.x;
    float r4 = a1.y - a1.w * p1.y;
    float r5 = a1.z - a1.w * p1.z;
    float r6 = a2.x - a2.w * p2.x;
    float r7 = a2.y - a2.w * p2.y;
    float r8 = a2.z - a2.w * p2.z;
    float r9 = a3.x - a3.w * p3.x;
    float r10 = a3.y - a3.w * p3.y;
    float r11 = a3.z - a3.w * p3.z;

    float4* dst = (float4*)(out + (size_t)v0 * 3);  // 48B per thread, 16B aligned
    dst[0] = make_float4(r0, r1, r2, r3);
    dst[1] = make_float4(r4, r5, r6, r7);
    dst[2] = make_float4(r8, r9, r10, r11);
}

extern "C" void kernel_launch(void* const* d_in, const int* in_sizes, int n_in,
                              void* d_out, int out_size) {
    // Robust slot selection: V has BN*3 = 2.4M elements, F has TOTF*3 = 4.8M.
    const float* V;
    const void* F;
    int f_elems;
    if (in_sizes[0] == BN * 3) {
        V = (const float*)d_in[0];
        F = d_in[1];
        f_elems = in_sizes[1];
    } else {
        V = (const float*)d_in[1];
        F = d_in[0];
        f_elems = in_sizes[0];
    }
    float* out = (float*)d_out;

    prep_k<<<(BN / 4 + 255) / 256, 256>>>(V, (const long long*)F, f_elems / 2);
    face_k<<<(TOTF + 255) / 256, 256>>>(F);
    fin_k<<<(BN / 4 + 255) / 256, 256>>>(out);
}

// round 10
// speedup vs baseline: 1.1289x; 1.1289x over previous
#include <cuda_runtime.h>

#define NB 8
#define NV 100000
#define NF 200000
#define BN (NB * NV)
#define TOTF (NB * NF)

// scratch: per-vertex accumulator (x, y, z, deg) — 12.8 MB, L2-resident
__device__ float4 g_acc[BN];
// padded, 16B-aligned copy of V for single-LDG.128 gathers
__device__ float4 g_V4[BN];
__device__ int g_is32;   // 1 if F is int32, 0 if int64

// Prep: dtype detect (parallel, warp 0 of block 0) + zero accumulators
// + pad V into float4 staging. ONE vertex per thread (max parallelism —
// measured faster than 4-vtx/thread on this chip for streaming).
__global__ void __launch_bounds__(256) prep_k(const float* __restrict__ V,
                                              const long long* __restrict__ F64,
                                              int nwords) {
    int v = blockIdx.x * blockDim.x + threadIdx.x;

    if (blockIdx.x == 0 && threadIdx.x < 32) {
        int lane = threadIdx.x;
        int bad = 0;
        int n = nwords < 1024 ? nwords : 1024;
        #pragma unroll
        for (int k = 0; k < 32; k++) {
            int i = lane + k * 32;
            if (i < n) {
                long long x = F64[i];
                bad |= (x < 0 || x >= NV) ? 1 : 0;
            }
        }
        unsigned m = __ballot_sync(0xFFFFFFFFu, bad);
        if (lane == 0) g_is32 = (m != 0) ? 1 : 0;
    }

    if (v >= BN) return;
    const float* p = V + (size_t)v * 3;
    g_V4[v] = make_float4(p[0], p[1], p[2], 0.f);
    g_acc[v] = make_float4(0.f, 0.f, 0.f, 0.f);
}

__device__ __forceinline__ int clampi(int v, int lo, int hi) {
    return v < lo ? lo : (v > hi ? hi : v);
}

__device__ __forceinline__ void red_v4(float4* addr, float x, float y, float z, float w) {
    asm volatile("red.global.add.v4.f32 [%0], {%1, %2, %3, %4};"
                 :: "l"(addr), "f"(x), "f"(y), "f"(z), "f"(w)
                 : "memory");
}

// Core per-face computation: gathers already in registers.
__device__ __forceinline__ void face_body(int i0, int i1, int i2,
                                          float4 P0, float4 P1, float4 P2) {
    float x0 = P0.x, y0 = P0.y, z0 = P0.z;
    float x1 = P1.x, y1 = P1.y, z1 = P1.z;
    float x2 = P2.x, y2 = P2.y, z2 = P2.z;

    float ax = x1 - x2, ay = y1 - y2, az = z1 - z2;
    float bx = x2 - x0, by = y2 - y0, bz = z2 - z0;
    float cx = x0 - x1, cy = y0 - y1, cz = z0 - z1;
    float d1 = ax * ax + ay * ay + az * az;
    float d2 = bx * bx + by * by + bz * bz;
    float d3 = cx * cx + cy * cy + cz * cz;
    float l1 = sqrtf(d1), l2 = sqrtf(d2), l3 = sqrtf(d3);
    float sp = 0.5f * (l1 + l2 + l3);
    float inside = sp * (sp - l1) * (sp - l2) * (sp - l3);
    inside = fmaxf(inside, 0.0f);
    float A = 2.0f * sqrtf(inside);
    float inv = 0.25f / (A + 1e-10f);
    if (A == 0.0f) inv = 0.0f;

    float w23 = (d2 + d3 - d1) * inv;  // edge (v1,v2)
    float w31 = (d1 + d3 - d2) * inv;  // edge (v2,v0)
    float w12 = (d1 + d2 - d3) * inv;  // edge (v0,v1)

    red_v4(&g_acc[i0], w31 * x2 + w12 * x1, w31 * y2 + w12 * y1,
                       w31 * z2 + w12 * z1, w31 + w12);
    red_v4(&g_acc[i1], w23 * x2 + w12 * x0, w23 * y2 + w12 * y0,
                       w23 * z2 + w12 * z0, w23 + w12);
    red_v4(&g_acc[i2], w23 * x1 + w31 * x0, w23 * y1 + w31 * y0,
                       w23 * z1 + w31 * z0, w23 + w31);
}

// Two faces per thread: 16B-aligned index loads + 6 gathers in flight.
// A face pair (2t, 2t+1) never straddles a batch boundary (NF even).
__global__ void __launch_bounds__(256) face_k(const void* __restrict__ Fraw) {
    int t = blockIdx.x * blockDim.x + threadIdx.x;
    if (t >= TOTF / 2) return;
    int face0 = t * 2;
    int b = face0 / NF;
    int base = b * NV;

    int fa0, fa1, fa2, fb0, fb1, fb2;
    if (g_is32) {
        const int* fp = (const int*)Fraw + (size_t)face0 * 3;
        fa0 = fp[0]; fa1 = fp[1]; fa2 = fp[2];
        fb0 = fp[3]; fb1 = fp[4]; fb2 = fp[5];
    } else {
        // 6 int64 = 48B, 16B-aligned: three longlong2 loads
        const longlong2* fp = (const longlong2*)((const long long*)Fraw + (size_t)face0 * 3);
        longlong2 q0 = __ldg(&fp[0]);
        longlong2 q1 = __ldg(&fp[1]);
        longlong2 q2 = __ldg(&fp[2]);
        fa0 = (int)q0.x; fa1 = (int)q0.y; fa2 = (int)q1.x;
        fb0 = (int)q1.y; fb1 = (int)q2.x; fb2 = (int)q2.y;
    }
    fa0 = clampi(fa0, 0, NV - 1); fa1 = clampi(fa1, 0, NV - 1); fa2 = clampi(fa2, 0, NV - 1);
    fb0 = clampi(fb0, 0, NV - 1); fb1 = clampi(fb1, 0, NV - 1); fb2 = clampi(fb2, 0, NV - 1);

    int ia0 = base + fa0, ia1 = base + fa1, ia2 = base + fa2;
    int ib0 = base + fb0, ib1 = base + fb1, ib2 = base + fb2;

    // issue all six gathers before any compute (MLP)
    float4 A0 = __ldg(&g_V4[ia0]);
    float4 A1 = __ldg(&g_V4[ia1]);
    float4 A2 = __ldg(&g_V4[ia2]);
    float4 B0 = __ldg(&g_V4[ib0]);
    float4 B1 = __ldg(&g_V4[ib1]);
    float4 B2 = __ldg(&g_V4[ib2]);

    face_body(ia0, ia1, ia2, A0, A1, A2);
    face_body(ib0, ib1, ib2, B0, B1, B2);
}

// out[v] = acc[v].xyz - acc[v].w * V[v], one vertex per thread.
__global__ void __launch_bounds__(256) fin_k(float* __restrict__ out) {
    int v = blockIdx.x * blockDim.x + threadIdx.x;
    if (v < BN) {
        float4 a = g_acc[v];
        float4 p = g_V4[v];
        float* o = out + (size_t)v * 3;
        o[0] = a.x - a.w * p.x;
        o[1] = a.y - a.w * p.y;
        o[2] = a.z - a.w * p.z;
    }
}

extern "C" void kernel_launch(void* const* d_in, const int* in_sizes, int n_in,
                              void* d_out, int out_size) {
    // Robust slot selection: V has BN*3 = 2.4M elements, F has TOTF*3 = 4.8M.
    const float* V;
    const void* F;
    int f_elems;
    if (in_sizes[0] == BN * 3) {
        V = (const float*)d_in[0];
        F = d_in[1];
        f_elems = in_sizes[1];
    } else {
        V = (const float*)d_in[1];
        F = d_in[0];
        f_elems = in_sizes[0];
    }
    float* out = (float*)d_out;

    prep_k<<<(BN + 255) / 256, 256>>>(V, (const long long*)F, f_elems / 2);
    face_k<<<(TOTF / 2 + 255) / 256, 256>>>(F);
    fin_k<<<(BN + 255) / 256, 256>>>(out);
}